// round 2
// baseline (speedup 1.0000x reference)
#include <cuda_runtime.h>
#include <cuda_bf16.h>

#define RPB   32     // rows per block
#define BLOCK 256

#define PI_F 3.14159265358979f

// Abramowitz-Stegun 4.4.46: acos(x) = sqrt(1-x)*poly7(x) for x in [0,1],
// abs error <= 2e-8. Extended to [-1,1] via acos(-x) = pi - acos(x).
__device__ __forceinline__ float acos_fast(float x) {
    float ax = fabsf(x);
    float p = fmaf(ax, -0.0012624911f, 0.0066700901f);
    p = fmaf(ax, p, -0.0170881256f);
    p = fmaf(ax, p,  0.0308918810f);
    p = fmaf(ax, p, -0.0501743046f);
    p = fmaf(ax, p,  0.0889789874f);
    p = fmaf(ax, p, -0.2145988016f);
    p = fmaf(ax, p,  1.5707963050f);
    float r = sqrtf(1.0f - ax) * p;
    return (x < 0.0f) ? (PI_F - r) : r;
}

__global__ __launch_bounds__(BLOCK)
void giou_loss_kernel(const float* __restrict__ pred,
                      const float* __restrict__ target,
                      float* __restrict__ out, int N) {
    __shared__ __align__(16) float s_t[RPB * 50];
    __shared__ __align__(16) float s_p[RPB * 26];
    __shared__ float s_dist[RPB];

    const int r0  = blockIdx.x * RPB;
    const int tid = threadIdx.x;
    const int rows = min(RPB, N - r0);
    if (rows <= 0) return;

    // ---- Stage tiles into smem (coalesced float4 loads on the full-tile path) ----
    if (rows == RPB) {
        const float4* tg = reinterpret_cast<const float4*>(target + (size_t)r0 * 50);
        float4* st4 = reinterpret_cast<float4*>(s_t);
        for (int i = tid; i < RPB * 50 / 4; i += BLOCK) st4[i] = tg[i];
        const float4* pg = reinterpret_cast<const float4*>(pred + (size_t)r0 * 26);
        float4* sp4 = reinterpret_cast<float4*>(s_p);
        for (int i = tid; i < RPB * 26 / 4; i += BLOCK) sp4[i] = pg[i];
    } else {
        for (int i = tid; i < rows * 50; i += BLOCK) s_t[i] = target[(size_t)r0 * 50 + i];
        for (int i = tid; i < rows * 26; i += BLOCK) s_p[i] = pred[(size_t)r0 * 26 + i];
    }
    __syncthreads();

    // ---- Per-row: dist, pd_cx/pd_cy outputs ----
    if (tid < rows) {
        float pcx = s_p[tid * 26 + 0];
        float pcy = s_p[tid * 26 + 1];
        float gcx = s_t[tid * 50 + 0];
        float gcy = s_t[tid * 50 + 1];
        float dx = gcx - pcx, dy = gcy - pcy;
        s_dist[tid] = sqrtf(dx * dx + dy * dy);
        out[(size_t)N * 24 + r0 + tid] = pcx;
        out[(size_t)N * 25 + r0 + tid] = pcy;
    }
    __syncthreads();

    // ---- Per (row, j) element: 24 per row ----
    float* __restrict__ out_loss  = out;                       // [N*24]
    float* __restrict__ out_scale = out + (size_t)N * 26;      // [N*24]
    const int items = rows * 24;

    for (int it = tid; it < items; it += BLOCK) {
        const int r = it / 24;
        const int j = it - r * 24;
        const float* t = s_t + r * 50;
        const float* p = s_p + r * 26;

        const float gt_cx = t[0], gt_cy = t[1];
        const float gx = t[2 + 2 * j], gy = t[3 + 2 * j];
        const float vx = gx - gt_cx, vy = gy - gt_cy;
        const float sg = sqrtf(vx * vx + vy * vy);   // scale_gt
        const float sp = p[2 + j];                   // scale_pd
        const float dist = s_dist[r];

        const float minr = fminf(sg, sp);
        const float maxr = fmaxf(sg, sp);
        const float minr2 = minr * minr;
        const float maxr2 = maxr * maxr;
        const float d2    = dist * dist;

        float acmin = __fdividef(minr2 + d2 - maxr2, 2.0f * minr * dist + 1e-8f);
        float acmax = __fdividef(maxr2 + d2 - minr2, 2.0f * maxr * dist + 1e-8f);
        acmin = fminf(fmaxf(acmin, -0.99f), 0.99f);
        acmax = fminf(fmaxf(acmax, -0.99f), 0.99f);

        const float ang_min = acos_fast(acmin);
        const float ang_max = acos_fast(acmax);
        // sin(acos(x)) = sqrt(1 - x^2), exact for angle in [0, pi]
        const float sin_min = sqrtf(fmaxf(1.0f - acmin * acmin, 0.0f));

        const float inter = ang_min * minr2 + ang_max * maxr2 - minr * dist * sin_min;

        const bool contained = fabsf(sg - sp) >= dist;
        const bool disjoint  = dist >= sg + sp;
        const float res = disjoint ? 0.0f : (contained ? PI_F * minr2 : inter);

        const float area = PI_F * (sg * sg) + PI_F * (sp * sp);  // area_gt + area_pd
        const float iou  = __fdividef(res, area - res + 1e-6f);

        const float cl = contained ? maxr : 0.5f * (sg + sp + dist);
        const float cs = PI_F * cl * cl;
        const float top = cs - (area - res);
        const float giou = iou - __fdividef(top, cs);

        out_loss [(size_t)r0 * 24 + it] = 1.0f - giou;
        out_scale[(size_t)r0 * 24 + it] = sp;
    }
}

extern "C" void kernel_launch(void* const* d_in, const int* in_sizes, int n_in,
                              void* d_out, int out_size) {
    const float* pred   = (const float*)d_in[0];
    const float* target = (const float*)d_in[1];
    float* out = (float*)d_out;
    int N = in_sizes[0] / 26;
    int grid = (N + RPB - 1) / RPB;
    giou_loss_kernel<<<grid, BLOCK>>>(pred, target, out, N);
}